// round 14
// baseline (speedup 1.0000x reference)
#include <cuda_runtime.h>
#include <cstddef>
#include <cstdint>

// Croston's method — fused kernel, round 14.
// 64-thread blocks, one row per block, cp.async staging.
// Each thread owns TWO 16-element segments (two independent dependency
// chains) and all recurrences use the short-chain form s' = omz*s + anz*t
// (single loop-carried FMA). Affine maps tracked as (A,Bz,D,F); C and E
// derived via the invariant C = A*kc*[A!=1], E = [A==1] (kc = a/(1-a)).
// Genuine exclusive scan: in-warp inclusive Kogge-Stone + shfl-up shift +
// cross-warp fixup through smem.

static constexpr int T_LEN   = 2048;
static constexpr int B_ROWS  = 8192;
static constexpr int THREADS = 64;
static constexpr int S4      = 9;    // float4 slot per thread (8 data + pad)

__device__ __forceinline__ uint32_t smem_u32(const void* p) {
    uint32_t a;
    asm("{ .reg .u64 t; cvta.to.shared.u64 t, %1; cvt.u32.u64 %0, t; }"
        : "=r"(a) : "l"(p));
    return a;
}

// compose: mine(A,Bz,D,F) := mine ∘ prev   (prev applied first)
__device__ __forceinline__ void map_compose(
    float& A, float& Bz, float& D, float& F,
    float pA, float pB, float pD, float pF, float kc)
{
    bool  nzm = (A != 1.0f);
    float Cm  = nzm ? A * kc : 0.0f;
    float Em  = nzm ? 0.0f : 1.0f;
    Bz = fmaf(A, pB, Bz);
    D  = fmaf(A, pD, fmaf(Cm, pF, D));
    F  = fmaf(Em, pF, F);
    A  = A * pA;
}

__global__ __launch_bounds__(THREADS, 21) void croston_fused_kernel(
    const float* __restrict__ x,
    const float* __restrict__ alpha,
    const float* __restrict__ Z0,
    const float* __restrict__ V0,
    const float* __restrict__ q0,
    float* __restrict__ out)
{
    __shared__ float4 sx[THREADS * S4];   // 9216 B
    __shared__ float  swtot[4];           // lower-warp inclusive total

    int tx = threadIdx.x;
    int b  = blockIdx.x;

    // ── 1. staging via cp.async: 512 float4, slot = p + (p>>3) ──
    {
        const float4* gx = reinterpret_cast<const float4*>(x + (size_t)b * T_LEN);
        #pragma unroll
        for (int i = 0; i < 8; i++) {
            int p = i * THREADS + tx;
            uint32_t dst = smem_u32(&sx[p + (p >> 3)]);
            asm volatile("cp.async.cg.shared.global [%0], [%1], 16;\n"
                         :: "r"(dst), "l"(gx + p));
        }
        asm volatile("cp.async.commit_group;\n");
    }

    float a  = __ldg(alpha);
    float kc = __fdividef(a, 1.0f - a);

    int lane = tx & 31;
    int half = tx >> 5;

    float Zi = __ldg(Z0 + b);
    float Vi = __ldg(V0 + b);
    float qi = __ldg(q0 + b);

    asm volatile("cp.async.wait_group 0;\n" ::: "memory");
    __syncthreads();

    float4* seg4 = &sx[tx * S4];   // [0..3] = seg 2t, [4..7] = seg 2t+1

    // ── 2. build the two segment maps with interleaved chains ──
    float A0 = 1.0f, B0 = 0.0f, D0 = 0.0f, F0 = 0.0f;
    float A1 = 1.0f, B1 = 0.0f, D1 = 0.0f, F1 = 0.0f;
    #pragma unroll
    for (int i = 0; i < 4; i++) {
        float4 va = seg4[i];
        float4 vb = seg4[i + 4];
        float xa[4] = {va.x, va.y, va.z, va.w};
        float xb[4] = {vb.x, vb.y, vb.z, vb.w};
        #pragma unroll
        for (int j = 0; j < 4; j++) {
            {   // chain A (segment 2t)
                float xt  = xa[j];
                float nzf = fminf(xt, 1.0f);
                float anz = a * nzf;
                float omz = 1.0f - anz;
                float ez  = 1.0f - nzf;
                B0 = fmaf(omz, B0, anz * xt);
                D0 = fmaf(omz, D0, anz * F0);   // pre-update F0
                A0 = A0 * omz;
                F0 = fmaf(ez, F0, 1.0f);
            }
            {   // chain B (segment 2t+1)
                float xt  = xb[j];
                float nzf = fminf(xt, 1.0f);
                float anz = a * nzf;
                float omz = 1.0f - anz;
                float ez  = 1.0f - nzf;
                B1 = fmaf(omz, B1, anz * xt);
                D1 = fmaf(omz, D1, anz * F1);
                A1 = A1 * omz;
                F1 = fmaf(ez, F1, 1.0f);
            }
        }
    }

    // thread-local map = mapB ∘ mapA
    float A = A1, Bz = B1, D = D1, F = F1;
    map_compose(A, Bz, D, F, A0, B0, D0, F0, kc);

    // ── 3. in-warp inclusive Kogge-Stone scan ──
    #pragma unroll
    for (int d = 1; d < 32; d <<= 1) {
        float pA = __shfl_up_sync(0xffffffffu, A,  d);
        float pB = __shfl_up_sync(0xffffffffu, Bz, d);
        float pD = __shfl_up_sync(0xffffffffu, D,  d);
        float pF = __shfl_up_sync(0xffffffffu, F,  d);
        if (lane >= d)
            map_compose(A, Bz, D, F, pA, pB, pD, pF, kc);
    }

    // lower warp publishes its inclusive total
    if (half == 0 && lane == 31) {
        swtot[0] = A; swtot[1] = Bz; swtot[2] = D; swtot[3] = F;
    }

    // exclusive shift (lane 0 = identity)
    {
        float eA = __shfl_up_sync(0xffffffffu, A,  1);
        float eB = __shfl_up_sync(0xffffffffu, Bz, 1);
        float eD = __shfl_up_sync(0xffffffffu, D,  1);
        float eF = __shfl_up_sync(0xffffffffu, F,  1);
        bool l0 = (lane == 0);
        A  = l0 ? 1.0f : eA;
        Bz = l0 ? 0.0f : eB;
        D  = l0 ? 0.0f : eD;
        F  = l0 ? 0.0f : eF;
    }

    __syncthreads();

    // upper warp composes with lower-warp total (lower applied first)
    if (half == 1) {
        map_compose(A, Bz, D, F, swtot[0], swtot[1], swtot[2], swtot[3], kc);
    }

    // state at the start of segment 2t
    float Za, Va, qa;
    {
        bool  nz = (A != 1.0f);
        float C  = nz ? A * kc : 0.0f;
        float E  = nz ? 0.0f : 1.0f;
        Za = fmaf(A, Zi, Bz);
        Va = fmaf(A, Vi, fmaf(C, qi, D));
        qa = fmaf(E, qi, F);
    }
    // state at the start of segment 2t+1 = mapA applied to (Za,Va,qa)
    float Zb, Vb, qb;
    {
        bool  nz = (A0 != 1.0f);
        float C  = nz ? A0 * kc : 0.0f;
        float E  = nz ? 0.0f : 1.0f;
        Zb = fmaf(A0, Za, B0);
        Vb = fmaf(A0, Va, fmaf(C, qa, D0));
        qb = fmaf(E, qa, F0);
    }

    // ── 4. replay both segments, interleaved chains, write in place ──
    #pragma unroll
    for (int i = 0; i < 4; i++) {
        float4 va = seg4[i];
        float4 vb = seg4[i + 4];
        float xa[4] = {va.x, va.y, va.z, va.w};
        float xb[4] = {vb.x, vb.y, vb.z, vb.w};
        float oa[4], ob[4];
        #pragma unroll
        for (int j = 0; j < 4; j++) {
            {   // chain A
                float xt  = xa[j];
                float nzf = fminf(xt, 1.0f);
                float anz = a * nzf;
                float omz = 1.0f - anz;
                float ez  = 1.0f - nzf;
                Za = fmaf(omz, Za, anz * xt);
                Va = fmaf(omz, Va, anz * qa);   // pre-update q
                qa = fmaf(ez, qa, 1.0f);
                oa[j] = __fdividef(Za, Va);
            }
            {   // chain B
                float xt  = xb[j];
                float nzf = fminf(xt, 1.0f);
                float anz = a * nzf;
                float omz = 1.0f - anz;
                float ez  = 1.0f - nzf;
                Zb = fmaf(omz, Zb, anz * xt);
                Vb = fmaf(omz, Vb, anz * qb);
                qb = fmaf(ez, qb, 1.0f);
                ob[j] = __fdividef(Zb, Vb);
            }
        }
        seg4[i]     = make_float4(oa[0], oa[1], oa[2], oa[3]);
        seg4[i + 4] = make_float4(ob[0], ob[1], ob[2], ob[3]);
    }

    __syncthreads();

    // ── 5. coalesced store ──
    {
        float4* gout = reinterpret_cast<float4*>(out + (size_t)b * T_LEN);
        #pragma unroll
        for (int i = 0; i < 8; i++) {
            int p = i * THREADS + tx;
            gout[p] = sx[p + (p >> 3)];
        }
    }
}

extern "C" void kernel_launch(void* const* d_in, const int* in_sizes, int n_in,
                              void* d_out, int out_size)
{
    const float* x     = (const float*)d_in[0];
    const float* alpha = (const float*)d_in[1];
    const float* Z0    = (const float*)d_in[2];
    const float* V0    = (const float*)d_in[3];
    const float* q0    = (const float*)d_in[4];
    float* out = (float*)d_out;

    croston_fused_kernel<<<B_ROWS, THREADS>>>(x, alpha, Z0, V0, q0, out);
}

// round 15
// speedup vs baseline: 1.0256x; 1.0256x over previous
#include <cuda_runtime.h>
#include <cstddef>
#include <cstdint>

// Croston's method — fused kernel, round 15.
// 64-thread blocks, one row per block, cp.async staging, streaming stores.
// Two independent 16-element chains per thread; diff-form updates
// (s' = s + anz*(t - s), 9 ops/elem map pass, 10 ops/elem replay pass).
// Affine maps tracked as (A,Bz,D,F); C,E derived via the invariant
// C = A*kc*[A!=1], E = [A==1] (kc = a/(1-a), om<1).
// Exclusive scan: in-warp inclusive Kogge-Stone + shfl shift + smem fixup.

static constexpr int T_LEN   = 2048;
static constexpr int B_ROWS  = 8192;
static constexpr int THREADS = 64;
static constexpr int S4      = 9;    // float4 slot per thread (8 data + pad)

__device__ __forceinline__ uint32_t smem_u32(const void* p) {
    uint32_t a;
    asm("{ .reg .u64 t; cvta.to.shared.u64 t, %1; cvt.u32.u64 %0, t; }"
        : "=r"(a) : "l"(p));
    return a;
}

// compose: mine(A,Bz,D,F) := mine ∘ prev   (prev applied first)
__device__ __forceinline__ void map_compose(
    float& A, float& Bz, float& D, float& F,
    float pA, float pB, float pD, float pF, float kc)
{
    bool  nzm = (A != 1.0f);
    float Cm  = nzm ? A * kc : 0.0f;
    float Em  = nzm ? 0.0f : 1.0f;
    Bz = fmaf(A, pB, Bz);
    D  = fmaf(A, pD, fmaf(Cm, pF, D));
    F  = fmaf(Em, pF, F);
    A  = A * pA;
}

__global__ __launch_bounds__(THREADS, 24) void croston_fused_kernel(
    const float* __restrict__ x,
    const float* __restrict__ alpha,
    const float* __restrict__ Z0,
    const float* __restrict__ V0,
    const float* __restrict__ q0,
    float* __restrict__ out)
{
    __shared__ float4 sx[THREADS * S4];   // 9216 B
    __shared__ float  swtot[4];           // lower-warp inclusive total

    int tx = threadIdx.x;
    int b  = blockIdx.x;

    // ── 1. staging via cp.async: 512 float4, slot = p + (p>>3) ──
    {
        const float4* gx = reinterpret_cast<const float4*>(x + (size_t)b * T_LEN);
        #pragma unroll
        for (int i = 0; i < 8; i++) {
            int p = i * THREADS + tx;
            uint32_t dst = smem_u32(&sx[p + (p >> 3)]);
            asm volatile("cp.async.cg.shared.global [%0], [%1], 16;\n"
                         :: "r"(dst), "l"(gx + p));
        }
        asm volatile("cp.async.commit_group;\n");
    }

    float a  = __ldg(alpha);
    float kc = __fdividef(a, 1.0f - a);

    int lane = tx & 31;
    int half = tx >> 5;

    float Zi = __ldg(Z0 + b);
    float Vi = __ldg(V0 + b);
    float qi = __ldg(q0 + b);

    asm volatile("cp.async.wait_group 0;\n" ::: "memory");
    __syncthreads();

    float4* seg4 = &sx[tx * S4];   // [0..3] = seg 2t, [4..7] = seg 2t+1

    // ── 2. build the two segment maps, interleaved chains, diff form ──
    float A0 = 1.0f, B0 = 0.0f, D0 = 0.0f, F0 = 0.0f;
    float A1 = 1.0f, B1 = 0.0f, D1 = 0.0f, F1 = 0.0f;
    #pragma unroll
    for (int i = 0; i < 4; i++) {
        float4 va = seg4[i];
        float4 vb = seg4[i + 4];
        float xa[4] = {va.x, va.y, va.z, va.w};
        float xb[4] = {vb.x, vb.y, vb.z, vb.w};
        #pragma unroll
        for (int j = 0; j < 4; j++) {
            {   // chain A (segment 2t)
                float xt  = xa[j];
                float nzf = fminf(xt, 1.0f);
                float anz = a * nzf;
                B0 = fmaf(anz, xt - B0, B0);
                D0 = fmaf(anz, F0 - D0, D0);        // pre-update F0
                A0 = fmaf(anz, -A0, A0);
                F0 = fmaf(1.0f - nzf, F0, 1.0f);
            }
            {   // chain B (segment 2t+1)
                float xt  = xb[j];
                float nzf = fminf(xt, 1.0f);
                float anz = a * nzf;
                B1 = fmaf(anz, xt - B1, B1);
                D1 = fmaf(anz, F1 - D1, D1);
                A1 = fmaf(anz, -A1, A1);
                F1 = fmaf(1.0f - nzf, F1, 1.0f);
            }
        }
    }

    // thread-local map = mapB ∘ mapA
    float A = A1, Bz = B1, D = D1, F = F1;
    map_compose(A, Bz, D, F, A0, B0, D0, F0, kc);

    // ── 3. in-warp inclusive Kogge-Stone scan ──
    #pragma unroll
    for (int d = 1; d < 32; d <<= 1) {
        float pA = __shfl_up_sync(0xffffffffu, A,  d);
        float pB = __shfl_up_sync(0xffffffffu, Bz, d);
        float pD = __shfl_up_sync(0xffffffffu, D,  d);
        float pF = __shfl_up_sync(0xffffffffu, F,  d);
        if (lane >= d)
            map_compose(A, Bz, D, F, pA, pB, pD, pF, kc);
    }

    // lower warp publishes its inclusive total
    if (half == 0 && lane == 31) {
        swtot[0] = A; swtot[1] = Bz; swtot[2] = D; swtot[3] = F;
    }

    // exclusive shift (lane 0 = identity)
    {
        float eA = __shfl_up_sync(0xffffffffu, A,  1);
        float eB = __shfl_up_sync(0xffffffffu, Bz, 1);
        float eD = __shfl_up_sync(0xffffffffu, D,  1);
        float eF = __shfl_up_sync(0xffffffffu, F,  1);
        bool l0 = (lane == 0);
        A  = l0 ? 1.0f : eA;
        Bz = l0 ? 0.0f : eB;
        D  = l0 ? 0.0f : eD;
        F  = l0 ? 0.0f : eF;
    }

    __syncthreads();

    // upper warp composes with lower-warp total (lower applied first)
    if (half == 1) {
        map_compose(A, Bz, D, F, swtot[0], swtot[1], swtot[2], swtot[3], kc);
    }

    // state at the start of segment 2t
    float Za, Va, qa;
    {
        bool  nz = (A != 1.0f);
        float C  = nz ? A * kc : 0.0f;
        float E  = nz ? 0.0f : 1.0f;
        Za = fmaf(A, Zi, Bz);
        Va = fmaf(A, Vi, fmaf(C, qi, D));
        qa = fmaf(E, qi, F);
    }
    // state at the start of segment 2t+1 = mapA applied to (Za,Va,qa)
    float Zb, Vb, qb;
    {
        bool  nz = (A0 != 1.0f);
        float C  = nz ? A0 * kc : 0.0f;
        float E  = nz ? 0.0f : 1.0f;
        Zb = fmaf(A0, Za, B0);
        Vb = fmaf(A0, Va, fmaf(C, qa, D0));
        qb = fmaf(E, qa, F0);
    }

    // ── 4. replay both segments, interleaved chains, write in place ──
    #pragma unroll
    for (int i = 0; i < 4; i++) {
        float4 va = seg4[i];
        float4 vb = seg4[i + 4];
        float xa[4] = {va.x, va.y, va.z, va.w};
        float xb[4] = {vb.x, vb.y, vb.z, vb.w};
        float oa[4], ob[4];
        #pragma unroll
        for (int j = 0; j < 4; j++) {
            {   // chain A
                float xt  = xa[j];
                float nzf = fminf(xt, 1.0f);
                float anz = a * nzf;
                Za = fmaf(anz, xt - Za, Za);
                Va = fmaf(anz, qa - Va, Va);        // pre-update q
                qa = fmaf(1.0f - nzf, qa, 1.0f);
                oa[j] = __fdividef(Za, Va);
            }
            {   // chain B
                float xt  = xb[j];
                float nzf = fminf(xt, 1.0f);
                float anz = a * nzf;
                Zb = fmaf(anz, xt - Zb, Zb);
                Vb = fmaf(anz, qb - Vb, Vb);
                qb = fmaf(1.0f - nzf, qb, 1.0f);
                ob[j] = __fdividef(Zb, Vb);
            }
        }
        seg4[i]     = make_float4(oa[0], oa[1], oa[2], oa[3]);
        seg4[i + 4] = make_float4(ob[0], ob[1], ob[2], ob[3]);
    }

    __syncthreads();

    // ── 5. coalesced streaming store (evict-first: keep x resident in L2) ──
    {
        float4* gout = reinterpret_cast<float4*>(out + (size_t)b * T_LEN);
        #pragma unroll
        for (int i = 0; i < 8; i++) {
            int p = i * THREADS + tx;
            __stcs(gout + p, sx[p + (p >> 3)]);
        }
    }
}

extern "C" void kernel_launch(void* const* d_in, const int* in_sizes, int n_in,
                              void* d_out, int out_size)
{
    const float* x     = (const float*)d_in[0];
    const float* alpha = (const float*)d_in[1];
    const float* Z0    = (const float*)d_in[2];
    const float* V0    = (const float*)d_in[3];
    const float* q0    = (const float*)d_in[4];
    float* out = (float*)d_out;

    croston_fused_kernel<<<B_ROWS, THREADS>>>(x, alpha, Z0, V0, q0, out);
}

// round 16
// speedup vs baseline: 1.1055x; 1.0779x over previous
#include <cuda_runtime.h>
#include <cstddef>
#include <cstdint>

// Croston's method — fused kernel, round 16: packed f32x2 dual chains.
// 64-thread blocks, one row per block, cp.async staging, streaming stores.
// Each thread owns two 16-element segments; the two chains live in the
// lo/hi halves of 64-bit f32x2 register pairs, so the per-element state
// updates use fma.rn.f32x2 / mul.rn.f32x2 (SASS FFMA2) — 2 elements per
// instruction. omz-form updates (omz = fma(nzf,-a,1)) avoid subtracts so
// everything maps onto mul/fma. Affine maps tracked as (A,Bz,D,F); C,E
// derived via C = A*kc*[A!=1], E = [A==1]. Scalar Kogge-Stone scan.

static constexpr int T_LEN   = 2048;
static constexpr int B_ROWS  = 8192;
static constexpr int THREADS = 64;
static constexpr int S4      = 9;    // float4 slot per thread (8 data + pad)

using u64 = unsigned long long;

__device__ __forceinline__ uint32_t smem_u32(const void* p) {
    uint32_t a;
    asm("{ .reg .u64 t; cvta.to.shared.u64 t, %1; cvt.u32.u64 %0, t; }"
        : "=r"(a) : "l"(p));
    return a;
}

__device__ __forceinline__ u64 pk2(float lo, float hi) {
    u64 r; asm("mov.b64 %0, {%1, %2};" : "=l"(r) : "f"(lo), "f"(hi)); return r;
}
__device__ __forceinline__ void upk2(float& lo, float& hi, u64 v) {
    asm("mov.b64 {%0, %1}, %2;" : "=f"(lo), "=f"(hi) : "l"(v));
}
#define FMA2(d, a, b, c) asm("fma.rn.f32x2 %0, %1, %2, %3;" \
                             : "=l"(d) : "l"(a), "l"(b), "l"(c))
#define MUL2(d, a, b)    asm("mul.rn.f32x2 %0, %1, %2;" \
                             : "=l"(d) : "l"(a), "l"(b))

// compose: mine(A,Bz,D,F) := mine ∘ prev   (prev applied first) — scalar
__device__ __forceinline__ void map_compose(
    float& A, float& Bz, float& D, float& F,
    float pA, float pB, float pD, float pF, float kc)
{
    bool  nzm = (A != 1.0f);
    float Cm  = nzm ? A * kc : 0.0f;
    float Em  = nzm ? 0.0f : 1.0f;
    Bz = fmaf(A, pB, Bz);
    D  = fmaf(A, pD, fmaf(Cm, pF, D));
    F  = fmaf(Em, pF, F);
    A  = A * pA;
}

__global__ __launch_bounds__(THREADS, 20) void croston_fused_kernel(
    const float* __restrict__ x,
    const float* __restrict__ alpha,
    const float* __restrict__ Z0,
    const float* __restrict__ V0,
    const float* __restrict__ q0,
    float* __restrict__ out)
{
    __shared__ float4 sx[THREADS * S4];   // 9216 B
    __shared__ float  swtot[4];           // lower-warp inclusive total

    int tx = threadIdx.x;
    int b  = blockIdx.x;

    // ── 1. staging via cp.async: 512 float4, slot = p + (p>>3) ──
    {
        const float4* gx = reinterpret_cast<const float4*>(x + (size_t)b * T_LEN);
        #pragma unroll
        for (int i = 0; i < 8; i++) {
            int p = i * THREADS + tx;
            uint32_t dst = smem_u32(&sx[p + (p >> 3)]);
            asm volatile("cp.async.cg.shared.global [%0], [%1], 16;\n"
                         :: "r"(dst), "l"(gx + p));
        }
        asm volatile("cp.async.commit_group;\n");
    }

    float a  = __ldg(alpha);
    float kc = __fdividef(a, 1.0f - a);

    const u64 one2    = pk2(1.0f, 1.0f);
    const u64 negone2 = pk2(-1.0f, -1.0f);
    const u64 a2      = pk2(a, a);
    const u64 nega2   = pk2(-a, -a);

    int lane = tx & 31;
    int half = tx >> 5;

    float Zi = __ldg(Z0 + b);
    float Vi = __ldg(V0 + b);
    float qi = __ldg(q0 + b);

    asm volatile("cp.async.wait_group 0;\n" ::: "memory");
    __syncthreads();

    float4* seg4 = &sx[tx * S4];   // [0..3] = seg 2t (chain A), [4..7] = seg 2t+1 (chain B)

    // ── 2. build both segment maps, packed f32x2 ──
    u64 A2 = one2, B2 = pk2(0.f, 0.f), D2 = pk2(0.f, 0.f), F2 = pk2(0.f, 0.f);
    #pragma unroll
    for (int i = 0; i < 4; i++) {
        float4 va = seg4[i];
        float4 vb = seg4[i + 4];
        float xa[4] = {va.x, va.y, va.z, va.w};
        float xb[4] = {vb.x, vb.y, vb.z, vb.w};
        #pragma unroll
        for (int j = 0; j < 4; j++) {
            float nzfa = fminf(xa[j], 1.0f);
            float nzfb = fminf(xb[j], 1.0f);
            u64 nzf2 = pk2(nzfa, nzfb);
            u64 x2   = pk2(xa[j], xb[j]);
            u64 anz2, omz2, ez2, t;
            MUL2(anz2, a2, nzf2);
            FMA2(omz2, nzf2, nega2, one2);     // 1 - a*nzf
            FMA2(ez2,  nzf2, negone2, one2);   // 1 - nzf
            MUL2(t, anz2, x2);
            FMA2(B2, omz2, B2, t);
            MUL2(t, anz2, F2);                 // pre-update F
            FMA2(D2, omz2, D2, t);
            MUL2(A2, A2, omz2);
            FMA2(F2, ez2, F2, one2);
        }
    }
    float A0, A1, B0, B1, D0, D1, F0, F1;
    upk2(A0, A1, A2); upk2(B0, B1, B2); upk2(D0, D1, D2); upk2(F0, F1, F2);

    // thread-local map = mapB ∘ mapA (scalar)
    float A = A1, Bz = B1, D = D1, F = F1;
    map_compose(A, Bz, D, F, A0, B0, D0, F0, kc);

    // ── 3. in-warp inclusive Kogge-Stone scan ──
    #pragma unroll
    for (int d = 1; d < 32; d <<= 1) {
        float pA = __shfl_up_sync(0xffffffffu, A,  d);
        float pB = __shfl_up_sync(0xffffffffu, Bz, d);
        float pD = __shfl_up_sync(0xffffffffu, D,  d);
        float pF = __shfl_up_sync(0xffffffffu, F,  d);
        if (lane >= d)
            map_compose(A, Bz, D, F, pA, pB, pD, pF, kc);
    }

    if (half == 0 && lane == 31) {
        swtot[0] = A; swtot[1] = Bz; swtot[2] = D; swtot[3] = F;
    }

    // exclusive shift (lane 0 = identity)
    {
        float eA = __shfl_up_sync(0xffffffffu, A,  1);
        float eB = __shfl_up_sync(0xffffffffu, Bz, 1);
        float eD = __shfl_up_sync(0xffffffffu, D,  1);
        float eF = __shfl_up_sync(0xffffffffu, F,  1);
        bool l0 = (lane == 0);
        A  = l0 ? 1.0f : eA;
        Bz = l0 ? 0.0f : eB;
        D  = l0 ? 0.0f : eD;
        F  = l0 ? 0.0f : eF;
    }

    __syncthreads();

    if (half == 1)
        map_compose(A, Bz, D, F, swtot[0], swtot[1], swtot[2], swtot[3], kc);

    // state at start of segment 2t, then 2t+1 via mapA
    float Za, Va, qa, Zb, Vb, qb;
    {
        bool  nz = (A != 1.0f);
        float C  = nz ? A * kc : 0.0f;
        float E  = nz ? 0.0f : 1.0f;
        Za = fmaf(A, Zi, Bz);
        Va = fmaf(A, Vi, fmaf(C, qi, D));
        qa = fmaf(E, qi, F);
    }
    {
        bool  nz = (A0 != 1.0f);
        float C  = nz ? A0 * kc : 0.0f;
        float E  = nz ? 0.0f : 1.0f;
        Zb = fmaf(A0, Za, B0);
        Vb = fmaf(A0, Va, fmaf(C, qa, D0));
        qb = fmaf(E, qa, F0);
    }

    // ── 4. replay both segments, packed f32x2, write in place ──
    u64 Z2 = pk2(Za, Zb), V2 = pk2(Va, Vb), q2 = pk2(qa, qb);
    #pragma unroll
    for (int i = 0; i < 4; i++) {
        float4 va = seg4[i];
        float4 vb = seg4[i + 4];
        float xa[4] = {va.x, va.y, va.z, va.w};
        float xb[4] = {vb.x, vb.y, vb.z, vb.w};
        float oa[4], ob[4];
        #pragma unroll
        for (int j = 0; j < 4; j++) {
            float nzfa = fminf(xa[j], 1.0f);
            float nzfb = fminf(xb[j], 1.0f);
            u64 nzf2 = pk2(nzfa, nzfb);
            u64 x2   = pk2(xa[j], xb[j]);
            u64 anz2, omz2, ez2, t;
            MUL2(anz2, a2, nzf2);
            FMA2(omz2, nzf2, nega2, one2);
            FMA2(ez2,  nzf2, negone2, one2);
            MUL2(t, anz2, x2);
            FMA2(Z2, omz2, Z2, t);
            MUL2(t, anz2, q2);                 // pre-update q
            FMA2(V2, omz2, V2, t);
            FMA2(q2, ez2, q2, one2);
            float Zl, Zh, Vl, Vh;
            upk2(Zl, Zh, Z2);
            upk2(Vl, Vh, V2);
            oa[j] = __fdividef(Zl, Vl);
            ob[j] = __fdividef(Zh, Vh);
        }
        seg4[i]     = make_float4(oa[0], oa[1], oa[2], oa[3]);
        seg4[i + 4] = make_float4(ob[0], ob[1], ob[2], ob[3]);
    }

    __syncthreads();

    // ── 5. coalesced streaming store (evict-first: keep x resident in L2) ──
    {
        float4* gout = reinterpret_cast<float4*>(out + (size_t)b * T_LEN);
        #pragma unroll
        for (int i = 0; i < 8; i++) {
            int p = i * THREADS + tx;
            __stcs(gout + p, sx[p + (p >> 3)]);
        }
    }
}

extern "C" void kernel_launch(void* const* d_in, const int* in_sizes, int n_in,
                              void* d_out, int out_size)
{
    const float* x     = (const float*)d_in[0];
    const float* alpha = (const float*)d_in[1];
    const float* Z0    = (const float*)d_in[2];
    const float* V0    = (const float*)d_in[3];
    const float* q0    = (const float*)d_in[4];
    float* out = (float*)d_out;

    croston_fused_kernel<<<B_ROWS, THREADS>>>(x, alpha, Z0, V0, q0, out);
}